// round 7
// baseline (speedup 1.0000x reference)
#include <cuda_runtime.h>
#include <math.h>
#include <stdint.h>

#define N_SRC 50000
#define N_DST 50000
#define E_NUM 800000
#define D_IN  64
#define HID   256
#define HEADS 4
#define FPH   64
#define N_ACT 16
#define G3    (3*HID)   // 768

// ---------------- scratch (device globals; no runtime allocation) ----------------
__device__ float g_fs[(size_t)N_SRC * HID];
__device__ float g_fd[(size_t)N_DST * HID];
__device__ float g_res[(size_t)N_DST * HID];
__device__ float g_x[(size_t)N_DST * HID];
__device__ float g_gi[(size_t)N_DST * G3];
__device__ float g_gh[(size_t)N_DST * G3];
__device__ int   g_deg[N_DST];
__device__ int   g_cursor[N_DST];
__device__ int   g_rowstart[N_DST + 1];
__device__ int   g_csrc[E_NUM];

// ---------------- helpers ----------------
__device__ __forceinline__ void tf32hl(float v, float& h, float& l) {
    asm("cvt.rna.tf32.f32 %0, %1;" : "=f"(h) : "f"(v));
    l = v - h;   // remainder; MMA truncates it to tf32 itself
}
__device__ __forceinline__ void split4f(float4 v, float4& h, float4& l) {
    tf32hl(v.x, h.x, l.x); tf32hl(v.y, h.y, l.y);
    tf32hl(v.z, h.z, l.z); tf32hl(v.w, h.w, l.w);
}

#define MMA_TF32(c, a, b)                                                      \
    asm volatile("mma.sync.aligned.m16n8k8.row.col.f32.tf32.tf32.f32 "        \
                 "{%0,%1,%2,%3}, {%4,%5,%6,%7}, {%8,%9}, {%0,%1,%2,%3};"      \
                 : "+f"((c)[0]), "+f"((c)[1]), "+f"((c)[2]), "+f"((c)[3])      \
                 : "r"((a)[0]), "r"((a)[1]), "r"((a)[2]), "r"((a)[3]),        \
                   "r"((b)[0]), "r"((b)[1]))

// ---------------- split-TF32 tensor-core GEMM v3 ----------------
// C[M,N] = A[M,K] @ op(B) + bias, fp32-accurate via 3-term tf32 split.
// 128x128x16 block tile, 512 threads (4x4 warp grid, 32x32 warp tile).
// hi/lo pre-split into smem at store time; double buffered; dynamic smem 80KB.
#define SKA 20     // [row][k] stride, conflict-free fragment access
#define SKB 136    // [k][n] stride for !BT B
#define TBUF 2560  // floats per buffer (128*20)

template <bool BT>
__global__ __launch_bounds__(512, 1)
void mmagemm(const float* __restrict__ A, const float* __restrict__ B,
             const float* __restrict__ bias, float* __restrict__ C,
             int M, int N, int K) {
    extern __shared__ float sm[];
    float* Ash = sm;                 // [2][TBUF]
    float* Asl = sm + 2 * TBUF;
    float* Bsh = sm + 4 * TBUF;
    float* Bsl = sm + 6 * TBUF;

    const int tid  = threadIdx.x;
    const int lane = tid & 31;
    const int warp = tid >> 5;
    const int wm   = warp >> 2;
    const int wn   = warp & 3;
    const int m0   = blockIdx.y * 128;
    const int n0   = blockIdx.x * 128;

    const int lrow = tid >> 2;           // 0..127
    const int lk4  = (tid & 3) * 4;      // 0,4,8,12
    const int bk   = tid >> 5;           // 0..15   (!BT B loader)
    const int bn4  = (tid & 31) * 4;     // 0..124

    const int nk = K / 16;
    float4 ra, rb;

    auto fetch = [&](int k0) {
        int r = m0 + lrow;
        ra = (r < M) ? *(const float4*)(A + (size_t)r * K + k0 + lk4)
                     : make_float4(0.f, 0.f, 0.f, 0.f);
        if (BT) rb = *(const float4*)(B + (size_t)(n0 + lrow) * K + k0 + lk4);
        else    rb = *(const float4*)(B + (size_t)(k0 + bk) * N + n0 + bn4);
    };
    auto storeTile = [&](int b) {
        int base = b * TBUF;
        float4 h4, l4;
        split4f(ra, h4, l4);
        *(float4*)&Ash[base + lrow * SKA + lk4] = h4;
        *(float4*)&Asl[base + lrow * SKA + lk4] = l4;
        split4f(rb, h4, l4);
        if (BT) {
            *(float4*)&Bsh[base + lrow * SKA + lk4] = h4;
            *(float4*)&Bsl[base + lrow * SKA + lk4] = l4;
        } else {
            *(float4*)&Bsh[base + bk * SKB + bn4] = h4;
            *(float4*)&Bsl[base + bk * SKB + bn4] = l4;
        }
    };

    float c[2][4][4] = {};

    fetch(0); storeTile(0);
    __syncthreads();

    const int gr = lane >> 2;
    const int gc = lane & 3;

    for (int t = 0; t < nk; t++) {
        if (t + 1 < nk) fetch((t + 1) * 16);

        const float* Abh = Ash + (t & 1) * TBUF;
        const float* Abl = Asl + (t & 1) * TBUF;
        const float* Bbh = Bsh + (t & 1) * TBUF;
        const float* Bbl = Bsl + (t & 1) * TBUF;

        #pragma unroll
        for (int k8 = 0; k8 < 16; k8 += 8) {
            uint32_t ah[2][4], al[2][4], bh[4][2], bl[4][2];
            #pragma unroll
            for (int mt = 0; mt < 2; mt++) {
                int mb = wm * 32 + mt * 16 + gr;
                int i0 = mb * SKA + k8 + gc;
                int i1 = (mb + 8) * SKA + k8 + gc;
                ah[mt][0] = __float_as_uint(Abh[i0]);
                ah[mt][1] = __float_as_uint(Abh[i1]);
                ah[mt][2] = __float_as_uint(Abh[i0 + 4]);
                ah[mt][3] = __float_as_uint(Abh[i1 + 4]);
                al[mt][0] = __float_as_uint(Abl[i0]);
                al[mt][1] = __float_as_uint(Abl[i1]);
                al[mt][2] = __float_as_uint(Abl[i0 + 4]);
                al[mt][3] = __float_as_uint(Abl[i1 + 4]);
            }
            #pragma unroll
            for (int nt = 0; nt < 4; nt++) {
                int nb = wn * 32 + nt * 8 + gr;
                int j0 = BT ? (nb * SKA + k8 + gc)     : ((k8 + gc) * SKB + nb);
                int j1 = BT ? (nb * SKA + k8 + 4 + gc) : ((k8 + 4 + gc) * SKB + nb);
                bh[nt][0] = __float_as_uint(Bbh[j0]);
                bh[nt][1] = __float_as_uint(Bbh[j1]);
                bl[nt][0] = __float_as_uint(Bbl[j0]);
                bl[nt][1] = __float_as_uint(Bbl[j1]);
            }
            #pragma unroll
            for (int mt = 0; mt < 2; mt++)
                #pragma unroll
                for (int nt = 0; nt < 4; nt++) {
                    MMA_TF32(c[mt][nt], ah[mt], bh[nt]);
                    MMA_TF32(c[mt][nt], ah[mt], bl[nt]);
                    MMA_TF32(c[mt][nt], al[mt], bh[nt]);
                }
        }

        if (t + 1 < nk) {
            storeTile((t + 1) & 1);
            __syncthreads();
        }
    }

    #pragma unroll
    for (int mt = 0; mt < 2; mt++) {
        #pragma unroll
        for (int nt = 0; nt < 4; nt++) {
            int row = m0 + wm * 32 + mt * 16 + gr;
            int col = n0 + wn * 32 + nt * 8 + gc * 2;
            float b0 = bias[col], b1 = bias[col + 1];
            if (row < M) {
                float2 v = make_float2(c[mt][nt][0] + b0, c[mt][nt][1] + b1);
                *(float2*)(C + (size_t)row * N + col) = v;
            }
            if (row + 8 < M) {
                float2 v = make_float2(c[mt][nt][2] + b0, c[mt][nt][3] + b1);
                *(float2*)(C + (size_t)(row + 8) * N + col) = v;
            }
        }
    }
}

#define GEMM_SMEM (8 * TBUF * 4)   // 81920 bytes

// ---------------- CSR build ----------------
__global__ void hist_kernel(const int* __restrict__ edst) {
    int e = blockIdx.x * blockDim.x + threadIdx.x;
    if (e < E_NUM) atomicAdd(&g_deg[edst[e]], 1);
}

__global__ void scan_kernel() {
    __shared__ int sh[1024];
    __shared__ int carry;
    int tid = threadIdx.x;
    if (tid == 0) carry = 0;
    __syncthreads();
    for (int base = 0; base < N_DST; base += 1024) {
        int v = (base + tid < N_DST) ? g_deg[base + tid] : 0;
        sh[tid] = v;
        __syncthreads();
        #pragma unroll
        for (int off = 1; off < 1024; off <<= 1) {
            int t = (tid >= off) ? sh[tid - off] : 0;
            __syncthreads();
            sh[tid] += t;
            __syncthreads();
        }
        if (base + tid < N_DST) g_rowstart[base + tid] = carry + sh[tid] - v;
        __syncthreads();
        if (tid == 0) carry += sh[1023];
        __syncthreads();
    }
    if (threadIdx.x == 0) g_rowstart[N_DST] = E_NUM;
}

__global__ void fill_kernel(const int* __restrict__ esrc, const int* __restrict__ edst) {
    int e = blockIdx.x * blockDim.x + threadIdx.x;
    if (e >= E_NUM) return;
    int d = edst[e];
    int pos = atomicAdd(&g_cursor[d], 1);
    g_csrc[g_rowstart[d] + pos] = esrc[e];
}

// ---------------- fused GAT node kernel (online softmax) ----------------
__global__ __launch_bounds__(128)
void gat_node_kernel(const float* __restrict__ attn) {
    const int i    = blockIdx.x;
    const int warp = threadIdx.x >> 5;    // head
    const int lane = threadIdx.x & 31;
    const int fo   = warp * FPH + lane * 2;

    const int beg = g_rowstart[i];
    const int end = g_rowstart[i + 1];

    const float2 fd = *(const float2*)(g_fd + (size_t)i * HID + fo);
    const float2 at = *(const float2*)(attn + fo);

    float m = -INFINITY, den = 0.0f, ax = 0.0f, ay = 0.0f;

    if (beg < end) {
        int s = g_csrc[beg];
        float2 f = *(const float2*)(g_fs + (size_t)s * HID + fo);
        for (int j = beg; j < end; j++) {
            float2 fn;
            if (j + 1 < end) {
                int sn = g_csrc[j + 1];
                fn = *(const float2*)(g_fs + (size_t)sn * HID + fo);
            }
            float v0 = f.x + fd.x; v0 = fmaxf(v0, 0.2f * v0);
            float v1 = f.y + fd.y; v1 = fmaxf(v1, 0.2f * v1);
            float sc = fmaf(v0, at.x, v1 * at.y);
            #pragma unroll
            for (int o = 16; o; o >>= 1) sc += __shfl_xor_sync(0xffffffffu, sc, o);

            float mn  = fmaxf(m, sc);
            float scl = __expf(m - mn);
            float ex  = __expf(sc - mn);
            den = fmaf(den, scl, ex);
            ax  = fmaf(ax, scl, ex * f.x);
            ay  = fmaf(ay, scl, ex * f.y);
            m = mn;
            f = fn;
        }
    }

    float inv = (den > 0.0f) ? (1.0f / den) : 0.0f;
    float2 rs = *(const float2*)(g_res + (size_t)i * HID + fo);
    float2 o;
    o.x = fmaxf(fmaf(ax, inv, rs.x), 0.0f);
    o.y = fmaxf(fmaf(ay, inv, rs.y), 0.0f);
    *(float2*)(g_x + (size_t)i * HID + fo) = o;
}

// ---------------- fused GRU elementwise + logits head ----------------
// block = 16 nodes, 256 threads. r = tid>>4 (row), tid&15 selects 16-col slab.
#define LPAD 260

__global__ __launch_bounds__(256)
void gru_logits_kernel(const float* __restrict__ h0, const float* __restrict__ Wout,
                       const float* __restrict__ bout, float* __restrict__ hout,
                       float* __restrict__ out) {
    __shared__ float sh[16 * LPAD];
    __shared__ float sWt[16 * LPAD];
    int tid = threadIdx.x;
    for (int t = tid; t < HID * N_ACT; t += 256) {
        int k = t >> 4, c = t & 15;
        sWt[c * LPAD + k] = Wout[t];    // transpose: sWt[col][k]
    }
    int r   = tid >> 4;
    int row = blockIdx.x * 16 + r;
    int c0  = (tid & 15) * 16;

    if (row < N_DST) {
        size_t b  = (size_t)row * G3;
        size_t hb = (size_t)row * HID;
        #pragma unroll
        for (int q = 0; q < 16; q += 4) {
            int j = c0 + q;
            float4 gir = *(const float4*)(g_gi + b + j);
            float4 ghr = *(const float4*)(g_gh + b + j);
            float4 giz = *(const float4*)(g_gi + b + HID + j);
            float4 ghz = *(const float4*)(g_gh + b + HID + j);
            float4 gin = *(const float4*)(g_gi + b + 2 * HID + j);
            float4 ghn = *(const float4*)(g_gh + b + 2 * HID + j);
            float4 h   = *(const float4*)(h0 + hb + j);
            float4 o;
            {
                float rr = 1.0f / (1.0f + expf(-(gir.x + ghr.x)));
                float zz = 1.0f / (1.0f + expf(-(giz.x + ghz.x)));
                float nn = tanhf(gin.x + rr * ghn.x);
                o.x = (1.0f - zz) * nn + zz * h.x;
            }
            {
                float rr = 1.0f / (1.0f + expf(-(gir.y + ghr.y)));
                float zz = 1.0f / (1.0f + expf(-(giz.y + ghz.y)));
                float nn = tanhf(gin.y + rr * ghn.y);
                o.y = (1.0f - zz) * nn + zz * h.y;
            }
            {
                float rr = 1.0f / (1.0f + expf(-(gir.z + ghr.z)));
                float zz = 1.0f / (1.0f + expf(-(giz.z + ghz.z)));
                float nn = tanhf(gin.z + rr * ghn.z);
                o.z = (1.0f - zz) * nn + zz * h.z;
            }
            {
                float rr = 1.0f / (1.0f + expf(-(gir.w + ghr.w)));
                float zz = 1.0f / (1.0f + expf(-(giz.w + ghz.w)));
                float nn = tanhf(gin.w + rr * ghn.w);
                o.w = (1.0f - zz) * nn + zz * h.w;
            }
            *(float4*)(hout + hb + j) = o;
            *(float4*)&sh[r * LPAD + j] = o;
        }
    }
    __syncthreads();

    if (row < N_DST) {
        int col = tid & 15;
        float acc = bout[col];
        const float4* hv = (const float4*)&sh[r * LPAD];
        const float4* wv = (const float4*)&sWt[col * LPAD];
        #pragma unroll
        for (int k4 = 0; k4 < HID / 4; k4++) {
            float4 a = hv[k4], w = wv[k4];
            acc = fmaf(a.x, w.x, acc);
            acc = fmaf(a.y, w.y, acc);
            acc = fmaf(a.z, w.z, acc);
            acc = fmaf(a.w, w.w, acc);
        }
        out[(size_t)row * N_ACT + col] = acc;
    }
}

// ---------------- launch ----------------
extern "C" void kernel_launch(void* const* d_in, const int* in_sizes, int n_in,
                              void* d_out, int out_size) {
    const float* feat_gt    = (const float*)d_in[0];
    const float* feat_agent = (const float*)d_in[1];
    const float* h0         = (const float*)d_in[2];
    const int*   edge_src   = (const int*)d_in[3];
    const int*   edge_dst   = (const int*)d_in[4];
    const float* W_src      = (const float*)d_in[5];
    const float* b_src      = (const float*)d_in[6];
    const float* W_dst      = (const float*)d_in[7];
    const float* b_dst      = (const float*)d_in[8];
    const float* attn       = (const float*)d_in[9];
    const float* W_res      = (const float*)d_in[10];
    const float* b_res      = (const float*)d_in[11];
    const float* W_ih       = (const float*)d_in[12];
    const float* W_hh       = (const float*)d_in[13];
    const float* b_ih       = (const float*)d_in[14];
    const float* b_hh       = (const float*)d_in[15];
    const float* W_out      = (const float*)d_in[16];
    const float* b_out      = (const float*)d_in[17];

    float* out_logits = (float*)d_out;
    float* out_h      = (float*)d_out + (size_t)N_DST * N_ACT;

    float *p_fs, *p_fd, *p_res, *p_x, *p_gi, *p_gh;
    int *p_deg, *p_cur;
    cudaGetSymbolAddress((void**)&p_fs,  g_fs);
    cudaGetSymbolAddress((void**)&p_fd,  g_fd);
    cudaGetSymbolAddress((void**)&p_res, g_res);
    cudaGetSymbolAddress((void**)&p_x,   g_x);
    cudaGetSymbolAddress((void**)&p_gi,  g_gi);
    cudaGetSymbolAddress((void**)&p_gh,  g_gh);
    cudaGetSymbolAddress((void**)&p_deg, g_deg);
    cudaGetSymbolAddress((void**)&p_cur, g_cursor);

    cudaFuncSetAttribute(mmagemm<false>, cudaFuncAttributeMaxDynamicSharedMemorySize, GEMM_SMEM);
    cudaFuncSetAttribute(mmagemm<true>,  cudaFuncAttributeMaxDynamicSharedMemorySize, GEMM_SMEM);

    const int MB = (N_DST + 127) / 128;

    // CSR build
    cudaMemsetAsync(p_deg, 0, N_DST * sizeof(int));
    cudaMemsetAsync(p_cur, 0, N_DST * sizeof(int));
    hist_kernel<<<(E_NUM + 255) / 256, 256>>>(edge_dst);
    scan_kernel<<<1, 1024>>>();
    fill_kernel<<<(E_NUM + 255) / 256, 256>>>(edge_src, edge_dst);

    // feature projections (K=64, N=256)
    mmagemm<false><<<dim3(HID / 128, MB), 512, GEMM_SMEM>>>(feat_gt,    W_src, b_src, p_fs,  N_SRC, HID, D_IN);
    mmagemm<false><<<dim3(HID / 128, MB), 512, GEMM_SMEM>>>(feat_agent, W_dst, b_dst, p_fd,  N_DST, HID, D_IN);
    mmagemm<false><<<dim3(HID / 128, MB), 512, GEMM_SMEM>>>(feat_agent, W_res, b_res, p_res, N_DST, HID, D_IN);

    // fused GAT: online softmax + aggregation + residual + ReLU
    gat_node_kernel<<<N_DST, 128>>>(attn);

    // GRU gates (A @ W^T, K=256, N=768)
    mmagemm<true><<<dim3(G3 / 128, MB), 512, GEMM_SMEM>>>(p_x, W_ih, b_ih, p_gi, N_DST, G3, HID);
    mmagemm<true><<<dim3(G3 / 128, MB), 512, GEMM_SMEM>>>(h0,  W_hh, b_hh, p_gh, N_DST, G3, HID);

    // fused GRU + logits
    gru_logits_kernel<<<(N_DST + 15) / 16, 256>>>(h0, W_out, b_out, out_h, out_logits);
}

// round 8
// speedup vs baseline: 1.2504x; 1.2504x over previous
#include <cuda_runtime.h>
#include <math.h>
#include <stdint.h>

#define N_SRC 50000
#define N_DST 50000
#define E_NUM 800000
#define D_IN  64
#define HID   256
#define HEADS 4
#define FPH   64
#define N_ACT 16
#define G3    (3*HID)   // 768

// ---------------- scratch (device globals; no runtime allocation) ----------------
__device__ float g_fs[(size_t)N_SRC * HID];
__device__ float g_fd[(size_t)N_DST * HID];
__device__ float g_res[(size_t)N_DST * HID];
__device__ float g_x[(size_t)N_DST * HID];
__device__ float g_gi[(size_t)N_DST * G3];
__device__ float g_gh[(size_t)N_DST * G3];
__device__ int   g_deg[N_DST];
__device__ int   g_cursor[N_DST];
__device__ int   g_rowstart[N_DST + 1];
__device__ int   g_csrc[E_NUM];

// ---------------- helpers ----------------
// pack (x,y) into bf16x2 hi word + bf16x2 lo-residual word
__device__ __forceinline__ void bfsplit2(float x, float y, uint32_t& h, uint32_t& l) {
    asm("cvt.rn.bf16x2.f32 %0, %1, %2;" : "=r"(h) : "f"(y), "f"(x));
    float hx = __uint_as_float(h << 16);
    float hy = __uint_as_float(h & 0xFFFF0000u);
    asm("cvt.rn.bf16x2.f32 %0, %1, %2;" : "=r"(l) : "f"(y - hy), "f"(x - hx));
}

#define MMA_BF16(c, a, b)                                                      \
    asm volatile("mma.sync.aligned.m16n8k16.row.col.f32.bf16.bf16.f32 "       \
                 "{%0,%1,%2,%3}, {%4,%5,%6,%7}, {%8,%9}, {%0,%1,%2,%3};"      \
                 : "+f"((c)[0]), "+f"((c)[1]), "+f"((c)[2]), "+f"((c)[3])      \
                 : "r"((a)[0]), "r"((a)[1]), "r"((a)[2]), "r"((a)[3]),        \
                   "r"((b)[0]), "r"((b)[1]))

// ---------------- split-BF16 tensor-core GEMM ----------------
// C[M,N] = A[M,K] @ op(B) + bias, ~fp32 accurate via 3-term bf16 split.
// 128x128x16 block tile, 512 threads (4x4 warp grid, 32x32 warp tile).
// Tiles stored as packed bf16x2 (hi and lo) with [row][k2] stride 12 (bank-clean).
#define SK12 12
#define TBUF (128 * SK12)   // 1536 u32 per tile buffer

template <bool BT>
__global__ __launch_bounds__(512, 1)
void mmagemm(const float* __restrict__ A, const float* __restrict__ B,
             const float* __restrict__ bias, float* __restrict__ C,
             int M, int N, int K) {
    extern __shared__ uint32_t sm[];
    uint32_t* Ash = sm;                // [2][TBUF]
    uint32_t* Asl = sm + 2 * TBUF;
    uint32_t* Bsh = sm + 4 * TBUF;
    uint32_t* Bsl = sm + 6 * TBUF;

    const int tid  = threadIdx.x;
    const int lane = tid & 31;
    const int warp = tid >> 5;
    const int wm   = warp >> 2;
    const int wn   = warp & 3;
    const int m0   = blockIdx.y * 128;
    const int n0   = blockIdx.x * 128;

    // A / BT-B loader: one float4 (4 k) per thread
    const int lrow = tid >> 2;           // 0..127
    const int lk4  = (tid & 3) * 4;      // 0,4,8,12
    // !BT B loader: k-pair + 2 n values per thread
    const int bkp  = tid & 7;            // k-pair 0..7 (k = 2*bkp, 2*bkp+1)
    const int bn2  = tid >> 3;           // 0..63 -> n = 2*bn2

    const int nk = K / 16;
    float4 ra, rb;
    float2 rb0, rb1;

    auto fetch = [&](int k0) {
        int r = m0 + lrow;
        ra = (r < M) ? *(const float4*)(A + (size_t)r * K + k0 + lk4)
                     : make_float4(0.f, 0.f, 0.f, 0.f);
        if (BT) {
            rb = *(const float4*)(B + (size_t)(n0 + lrow) * K + k0 + lk4);
        } else {
            rb0 = *(const float2*)(B + (size_t)(k0 + 2 * bkp)     * N + n0 + 2 * bn2);
            rb1 = *(const float2*)(B + (size_t)(k0 + 2 * bkp + 1) * N + n0 + 2 * bn2);
        }
    };
    auto storeTile = [&](int b) {
        int base = b * TBUF;
        uint32_t h0, l0, h1, l1;
        int r12 = lrow * SK12 + (lk4 >> 1);
        bfsplit2(ra.x, ra.y, h0, l0);
        bfsplit2(ra.z, ra.w, h1, l1);
        *(uint2*)&Ash[base + r12] = make_uint2(h0, h1);
        *(uint2*)&Asl[base + r12] = make_uint2(l0, l1);
        if (BT) {
            bfsplit2(rb.x, rb.y, h0, l0);
            bfsplit2(rb.z, rb.w, h1, l1);
            *(uint2*)&Bsh[base + r12] = make_uint2(h0, h1);
            *(uint2*)&Bsl[base + r12] = make_uint2(l0, l1);
        } else {
            // transpose-pack: pairs along k for each of the 2 n values
            bfsplit2(rb0.x, rb1.x, h0, l0);   // n = 2*bn2
            bfsplit2(rb0.y, rb1.y, h1, l1);   // n = 2*bn2+1
            Bsh[base + (2 * bn2)     * SK12 + bkp] = h0;
            Bsl[base + (2 * bn2)     * SK12 + bkp] = l0;
            Bsh[base + (2 * bn2 + 1) * SK12 + bkp] = h1;
            Bsl[base + (2 * bn2 + 1) * SK12 + bkp] = l1;
        }
    };

    float c[2][4][4] = {};

    fetch(0); storeTile(0);
    __syncthreads();

    const int gr = lane >> 2;
    const int gc = lane & 3;

    for (int t = 0; t < nk; t++) {
        if (t + 1 < nk) fetch((t + 1) * 16);

        const uint32_t* Abh = Ash + (t & 1) * TBUF;
        const uint32_t* Abl = Asl + (t & 1) * TBUF;
        const uint32_t* Bbh = Bsh + (t & 1) * TBUF;
        const uint32_t* Bbl = Bsl + (t & 1) * TBUF;

        uint32_t ah[2][4], al[2][4], bh[4][2], bl[4][2];
        #pragma unroll
        for (int mt = 0; mt < 2; mt++) {
            int base = (wm * 32 + mt * 16 + gr) * SK12;
            ah[mt][0] = Abh[base + gc];
            ah[mt][1] = Abh[base + 8 * SK12 + gc];
            ah[mt][2] = Abh[base + 4 + gc];
            ah[mt][3] = Abh[base + 8 * SK12 + 4 + gc];
            al[mt][0] = Abl[base + gc];
            al[mt][1] = Abl[base + 8 * SK12 + gc];
            al[mt][2] = Abl[base + 4 + gc];
            al[mt][3] = Abl[base + 8 * SK12 + 4 + gc];
        }
        #pragma unroll
        for (int nt = 0; nt < 4; nt++) {
            int base = (wn * 32 + nt * 8 + gr) * SK12;
            bh[nt][0] = Bbh[base + gc];
            bh[nt][1] = Bbh[base + 4 + gc];
            bl[nt][0] = Bbl[base + gc];
            bl[nt][1] = Bbl[base + 4 + gc];
        }
        #pragma unroll
        for (int mt = 0; mt < 2; mt++)
            #pragma unroll
            for (int nt = 0; nt < 4; nt++) {
                MMA_BF16(c[mt][nt], ah[mt], bh[nt]);
                MMA_BF16(c[mt][nt], ah[mt], bl[nt]);
                MMA_BF16(c[mt][nt], al[mt], bh[nt]);
            }

        if (t + 1 < nk) {
            storeTile((t + 1) & 1);
            __syncthreads();
        }
    }

    #pragma unroll
    for (int mt = 0; mt < 2; mt++) {
        #pragma unroll
        for (int nt = 0; nt < 4; nt++) {
            int row = m0 + wm * 32 + mt * 16 + gr;
            int col = n0 + wn * 32 + nt * 8 + gc * 2;
            float b0 = bias[col], b1 = bias[col + 1];
            if (row < M) {
                float2 v = make_float2(c[mt][nt][0] + b0, c[mt][nt][1] + b1);
                *(float2*)(C + (size_t)row * N + col) = v;
            }
            if (row + 8 < M) {
                float2 v = make_float2(c[mt][nt][2] + b0, c[mt][nt][3] + b1);
                *(float2*)(C + (size_t)(row + 8) * N + col) = v;
            }
        }
    }
}

#define GEMM_SMEM (8 * TBUF * 4)   // 49152 bytes

// ---------------- CSR build ----------------
__global__ void hist_kernel(const int* __restrict__ edst) {
    int e = blockIdx.x * blockDim.x + threadIdx.x;
    if (e < E_NUM) atomicAdd(&g_deg[edst[e]], 1);
}

__global__ void scan_kernel() {
    __shared__ int sh[1024];
    __shared__ int carry;
    int tid = threadIdx.x;
    if (tid == 0) carry = 0;
    __syncthreads();
    for (int base = 0; base < N_DST; base += 1024) {
        int v = (base + tid < N_DST) ? g_deg[base + tid] : 0;
        sh[tid] = v;
        __syncthreads();
        #pragma unroll
        for (int off = 1; off < 1024; off <<= 1) {
            int t = (tid >= off) ? sh[tid - off] : 0;
            __syncthreads();
            sh[tid] += t;
            __syncthreads();
        }
        if (base + tid < N_DST) g_rowstart[base + tid] = carry + sh[tid] - v;
        __syncthreads();
        if (tid == 0) carry += sh[1023];
        __syncthreads();
    }
    if (threadIdx.x == 0) g_rowstart[N_DST] = E_NUM;
}

__global__ void fill_kernel(const int* __restrict__ esrc, const int* __restrict__ edst) {
    int e = blockIdx.x * blockDim.x + threadIdx.x;
    if (e >= E_NUM) return;
    int d = edst[e];
    int pos = atomicAdd(&g_cursor[d], 1);
    g_csrc[g_rowstart[d] + pos] = esrc[e];
}

// ---------------- fused GAT node kernel (online softmax) ----------------
__global__ __launch_bounds__(128)
void gat_node_kernel(const float* __restrict__ attn) {
    const int i    = blockIdx.x;
    const int warp = threadIdx.x >> 5;    // head
    const int lane = threadIdx.x & 31;
    const int fo   = warp * FPH + lane * 2;

    const int beg = g_rowstart[i];
    const int end = g_rowstart[i + 1];

    const float2 fd = *(const float2*)(g_fd + (size_t)i * HID + fo);
    const float2 at = *(const float2*)(attn + fo);

    float m = -INFINITY, den = 0.0f, ax = 0.0f, ay = 0.0f;

    if (beg < end) {
        int s = g_csrc[beg];
        float2 f = *(const float2*)(g_fs + (size_t)s * HID + fo);
        for (int j = beg; j < end; j++) {
            float2 fn;
            if (j + 1 < end) {
                int sn = g_csrc[j + 1];
                fn = *(const float2*)(g_fs + (size_t)sn * HID + fo);
            }
            float v0 = f.x + fd.x; v0 = fmaxf(v0, 0.2f * v0);
            float v1 = f.y + fd.y; v1 = fmaxf(v1, 0.2f * v1);
            float sc = fmaf(v0, at.x, v1 * at.y);
            #pragma unroll
            for (int o = 16; o; o >>= 1) sc += __shfl_xor_sync(0xffffffffu, sc, o);

            float mn  = fmaxf(m, sc);
            float scl = __expf(m - mn);
            float ex  = __expf(sc - mn);
            den = fmaf(den, scl, ex);
            ax  = fmaf(ax, scl, ex * f.x);
            ay  = fmaf(ay, scl, ex * f.y);
            m = mn;
            f = fn;
        }
    }

    float inv = (den > 0.0f) ? (1.0f / den) : 0.0f;
    float2 rs = *(const float2*)(g_res + (size_t)i * HID + fo);
    float2 o;
    o.x = fmaxf(fmaf(ax, inv, rs.x), 0.0f);
    o.y = fmaxf(fmaf(ay, inv, rs.y), 0.0f);
    *(float2*)(g_x + (size_t)i * HID + fo) = o;
}

// ---------------- fused GRU elementwise + logits head ----------------
#define LPAD 260

__global__ __launch_bounds__(256)
void gru_logits_kernel(const float* __restrict__ h0, const float* __restrict__ Wout,
                       const float* __restrict__ bout, float* __restrict__ hout,
                       float* __restrict__ out) {
    __shared__ float sh[16 * LPAD];
    __shared__ float sWt[16 * LPAD];
    int tid = threadIdx.x;
    for (int t = tid; t < HID * N_ACT; t += 256) {
        int k = t >> 4, c = t & 15;
        sWt[c * LPAD + k] = Wout[t];
    }
    int r   = tid >> 4;
    int row = blockIdx.x * 16 + r;
    int c0  = (tid & 15) * 16;

    if (row < N_DST) {
        size_t b  = (size_t)row * G3;
        size_t hb = (size_t)row * HID;
        #pragma unroll
        for (int q = 0; q < 16; q += 4) {
            int j = c0 + q;
            float4 gir = *(const float4*)(g_gi + b + j);
            float4 ghr = *(const float4*)(g_gh + b + j);
            float4 giz = *(const float4*)(g_gi + b + HID + j);
            float4 ghz = *(const float4*)(g_gh + b + HID + j);
            float4 gin = *(const float4*)(g_gi + b + 2 * HID + j);
            float4 ghn = *(const float4*)(g_gh + b + 2 * HID + j);
            float4 h   = *(const float4*)(h0 + hb + j);
            float4 o;
            {
                float rr = 1.0f / (1.0f + expf(-(gir.x + ghr.x)));
                float zz = 1.0f / (1.0f + expf(-(giz.x + ghz.x)));
                float nn = tanhf(gin.x + rr * ghn.x);
                o.x = (1.0f - zz) * nn + zz * h.x;
            }
            {
                float rr = 1.0f / (1.0f + expf(-(gir.y + ghr.y)));
                float zz = 1.0f / (1.0f + expf(-(giz.y + ghz.y)));
                float nn = tanhf(gin.y + rr * ghn.y);
                o.y = (1.0f - zz) * nn + zz * h.y;
            }
            {
                float rr = 1.0f / (1.0f + expf(-(gir.z + ghr.z)));
                float zz = 1.0f / (1.0f + expf(-(giz.z + ghz.z)));
                float nn = tanhf(gin.z + rr * ghn.z);
                o.z = (1.0f - zz) * nn + zz * h.z;
            }
            {
                float rr = 1.0f / (1.0f + expf(-(gir.w + ghr.w)));
                float zz = 1.0f / (1.0f + expf(-(giz.w + ghz.w)));
                float nn = tanhf(gin.w + rr * ghn.w);
                o.w = (1.0f - zz) * nn + zz * h.w;
            }
            *(float4*)(hout + hb + j) = o;
            *(float4*)&sh[r * LPAD + j] = o;
        }
    }
    __syncthreads();

    if (row < N_DST) {
        int col = tid & 15;
        float acc = bout[col];
        const float4* hv = (const float4*)&sh[r * LPAD];
        const float4* wv = (const float4*)&sWt[col * LPAD];
        #pragma unroll
        for (int k4 = 0; k4 < HID / 4; k4++) {
            float4 a = hv[k4], w = wv[k4];
            acc = fmaf(a.x, w.x, acc);
            acc = fmaf(a.y, w.y, acc);
            acc = fmaf(a.z, w.z, acc);
            acc = fmaf(a.w, w.w, acc);
        }
        out[(size_t)row * N_ACT + col] = acc;
    }
}

// ---------------- launch ----------------
extern "C" void kernel_launch(void* const* d_in, const int* in_sizes, int n_in,
                              void* d_out, int out_size) {
    const float* feat_gt    = (const float*)d_in[0];
    const float* feat_agent = (const float*)d_in[1];
    const float* h0         = (const float*)d_in[2];
    const int*   edge_src   = (const int*)d_in[3];
    const int*   edge_dst   = (const int*)d_in[4];
    const float* W_src      = (const float*)d_in[5];
    const float* b_src      = (const float*)d_in[6];
    const float* W_dst      = (const float*)d_in[7];
    const float* b_dst      = (const float*)d_in[8];
    const float* attn       = (const float*)d_in[9];
    const float* W_res      = (const float*)d_in[10];
    const float* b_res      = (const float*)d_in[11];
    const float* W_ih       = (const float*)d_in[12];
    const float* W_hh       = (const float*)d_in[13];
    const float* b_ih       = (const float*)d_in[14];
    const float* b_hh       = (const float*)d_in[15];
    const float* W_out      = (const float*)d_in[16];
    const float* b_out      = (const float*)d_in[17];

    float* out_logits = (float*)d_out;
    float* out_h      = (float*)d_out + (size_t)N_DST * N_ACT;

    float *p_fs, *p_fd, *p_res, *p_x, *p_gi, *p_gh;
    int *p_deg, *p_cur;
    cudaGetSymbolAddress((void**)&p_fs,  g_fs);
    cudaGetSymbolAddress((void**)&p_fd,  g_fd);
    cudaGetSymbolAddress((void**)&p_res, g_res);
    cudaGetSymbolAddress((void**)&p_x,   g_x);
    cudaGetSymbolAddress((void**)&p_gi,  g_gi);
    cudaGetSymbolAddress((void**)&p_gh,  g_gh);
    cudaGetSymbolAddress((void**)&p_deg, g_deg);
    cudaGetSymbolAddress((void**)&p_cur, g_cursor);

    cudaFuncSetAttribute(mmagemm<false>, cudaFuncAttributeMaxDynamicSharedMemorySize, GEMM_SMEM);
    cudaFuncSetAttribute(mmagemm<true>,  cudaFuncAttributeMaxDynamicSharedMemorySize, GEMM_SMEM);

    const int MB = (N_DST + 127) / 128;

    // CSR build
    cudaMemsetAsync(p_deg, 0, N_DST * sizeof(int));
    cudaMemsetAsync(p_cur, 0, N_DST * sizeof(int));
    hist_kernel<<<(E_NUM + 255) / 256, 256>>>(edge_dst);
    scan_kernel<<<1, 1024>>>();
    fill_kernel<<<(E_NUM + 255) / 256, 256>>>(edge_src, edge_dst);

    // feature projections (K=64, N=256)
    mmagemm<false><<<dim3(HID / 128, MB), 512, GEMM_SMEM>>>(feat_gt,    W_src, b_src, p_fs,  N_SRC, HID, D_IN);
    mmagemm<false><<<dim3(HID / 128, MB), 512, GEMM_SMEM>>>(feat_agent, W_dst, b_dst, p_fd,  N_DST, HID, D_IN);
    mmagemm<false><<<dim3(HID / 128, MB), 512, GEMM_SMEM>>>(feat_agent, W_res, b_res, p_res, N_DST, HID, D_IN);

    // fused GAT: online softmax + aggregation + residual + ReLU
    gat_node_kernel<<<N_DST, 128>>>(attn);

    // GRU gates (A @ W^T, K=256, N=768)
    mmagemm<true><<<dim3(G3 / 128, MB), 512, GEMM_SMEM>>>(p_x, W_ih, b_ih, p_gi, N_DST, G3, HID);
    mmagemm<true><<<dim3(G3 / 128, MB), 512, GEMM_SMEM>>>(h0,  W_hh, b_hh, p_gh, N_DST, G3, HID);

    // fused GRU + logits
    gru_logits_kernel<<<(N_DST + 15) / 16, 256>>>(h0, W_out, b_out, out_h, out_logits);
}

// round 10
// speedup vs baseline: 1.4640x; 1.1708x over previous
#include <cuda_runtime.h>
#include <cuda_bf16.h>
#include <math.h>
#include <stdint.h>

#define N_SRC 50000
#define N_DST 50000
#define M_PAD 50048
#define E_NUM 800000
#define D_IN  64
#define HID   256
#define HEADS 4
#define FPH   64
#define N_ACT 16
#define G3    (3*HID)   // 768

// ---------------- scratch (device globals; no runtime allocation) ----------------
__device__ float g_fs[(size_t)N_SRC * HID];
__device__ float g_fd[(size_t)N_DST * HID];
__device__ float g_res[(size_t)N_DST * HID];
__device__ float g_gi[(size_t)N_DST * G3];
__device__ float g_gh[(size_t)N_DST * G3];
__device__ int   g_deg[N_DST];
__device__ int   g_cursor[N_DST];
__device__ int   g_rowstart[N_DST + 1];
__device__ int   g_csrc[E_NUM];

// bf16 hi/lo split operands (A matrices padded to M_PAD rows)
__device__ __nv_bfloat16 s_gt_h[(size_t)M_PAD * D_IN],  s_gt_l[(size_t)M_PAD * D_IN];
__device__ __nv_bfloat16 s_ag_h[(size_t)M_PAD * D_IN],  s_ag_l[(size_t)M_PAD * D_IN];
__device__ __nv_bfloat16 s_x_h [(size_t)M_PAD * HID],   s_x_l [(size_t)M_PAD * HID];
__device__ __nv_bfloat16 s_h_h [(size_t)M_PAD * HID],   s_h_l [(size_t)M_PAD * HID];
// weights as [N,K]
__device__ __nv_bfloat16 s_ws_h[HID * D_IN], s_ws_l[HID * D_IN];
__device__ __nv_bfloat16 s_wd_h[HID * D_IN], s_wd_l[HID * D_IN];
__device__ __nv_bfloat16 s_wr_h[HID * D_IN], s_wr_l[HID * D_IN];
__device__ __nv_bfloat16 s_wi_h[G3 * HID],   s_wi_l[G3 * HID];
__device__ __nv_bfloat16 s_wh_h[G3 * HID],   s_wh_l[G3 * HID];

// ---------------- helpers ----------------
__device__ __forceinline__ uint32_t smem_u32(const void* p) {
    uint32_t a;
    asm("{ .reg .u64 t; cvta.to.shared.u64 t, %1; cvt.u32.u64 %0, t; }" : "=r"(a) : "l"(p));
    return a;
}
__device__ __forceinline__ uint32_t swz(uint32_t o) { return o ^ ((o >> 3) & 0x70); }

__device__ __forceinline__ void bfsplit2(float x, float y, uint32_t& h, uint32_t& l) {
    asm("cvt.rn.bf16x2.f32 %0, %1, %2;" : "=r"(h) : "f"(y), "f"(x));
    float hx = __uint_as_float(h << 16);
    float hy = __uint_as_float(h & 0xFFFF0000u);
    asm("cvt.rn.bf16x2.f32 %0, %1, %2;" : "=r"(l) : "f"(y - hy), "f"(x - hx));
}

#define MMA_BF16(c, a, b0, b1)                                                 \
    asm volatile("mma.sync.aligned.m16n8k16.row.col.f32.bf16.bf16.f32 "       \
                 "{%0,%1,%2,%3}, {%4,%5,%6,%7}, {%8,%9}, {%0,%1,%2,%3};"      \
                 : "+f"((c)[0]), "+f"((c)[1]), "+f"((c)[2]), "+f"((c)[3])      \
                 : "r"((a)[0]), "r"((a)[1]), "r"((a)[2]), "r"((a)[3]),        \
                   "r"(b0), "r"(b1))

#define LDSM4(r, addr)                                                         \
    asm volatile("ldmatrix.sync.aligned.m8n8.x4.shared.b16 {%0,%1,%2,%3}, [%4];" \
                 : "=r"((r)[0]), "=r"((r)[1]), "=r"((r)[2]), "=r"((r)[3])      \
                 : "r"(addr))

#define CP16(dst, src)                                                         \
    asm volatile("cp.async.cg.shared.global [%0], [%1], 16;" :: "r"(dst), "l"(src))

// ---------------- bf16 split kernels ----------------
__global__ void split_kernel(const float* __restrict__ src, __nv_bfloat16* __restrict__ hi,
                             __nv_bfloat16* __restrict__ lo, int n4) {
    int i = blockIdx.x * blockDim.x + threadIdx.x;
    if (i >= n4) return;
    float4 v = ((const float4*)src)[i];
    uint32_t h0, l0, h1, l1;
    bfsplit2(v.x, v.y, h0, l0);
    bfsplit2(v.z, v.w, h1, l1);
    ((uint2*)hi)[i] = make_uint2(h0, h1);
    ((uint2*)lo)[i] = make_uint2(l0, l1);
}

// W [K=64, N=256] -> out [256][64] bf16 hi/lo
__global__ void wsplit_t_kernel(const float* __restrict__ W,
                                __nv_bfloat16* __restrict__ hi, __nv_bfloat16* __restrict__ lo) {
    int idx = blockIdx.x * 256 + threadIdx.x;   // 64*256 total
    int k = idx >> 8, n = idx & 255;
    float v = W[idx];
    __nv_bfloat16 h = __float2bfloat16(v);
    __nv_bfloat16 l = __float2bfloat16(v - __bfloat162float(h));
    hi[n * 64 + k] = h;
    lo[n * 64 + k] = l;
}

// ---------------- split-bf16 HMMA GEMM with cp.async + ldmatrix ----------------
// C[M,N] = A[M,K] @ B[N,K]^T + bias. 128x128 CTA tile, 512 thr (4x4 warps, 32x32 warp tile),
// K chunks of 64, double-buffered cp.async, SW128-swizzled tiles, ldmatrix fragments.
#define TCB_SMEM 132096

__global__ __launch_bounds__(512, 1)
void tcbgemm(const __nv_bfloat16* __restrict__ Ah, const __nv_bfloat16* __restrict__ Al,
             const __nv_bfloat16* __restrict__ Bh, const __nv_bfloat16* __restrict__ Bl,
             const float* __restrict__ bias, float* __restrict__ C,
             int M, int N, int K) {
    extern __shared__ char smraw[];
    uint32_t rawu = smem_u32(smraw);
    const uint32_t ub = rawu + ((1024u - (rawu & 1023u)) & 1023u);

    const int tid  = threadIdx.x;
    const int lane = tid & 31;
    const int warp = tid >> 5;
    const int wm   = warp >> 2;          // 0..3
    const int wn   = warp & 3;           // 0..3
    const int m0   = blockIdx.y * 128;
    const int n0   = blockIdx.x * 128;
    const int nch  = K / 64;

    // loader indices: 2 iterations x (row, 16B-chunk) per tile
    const int lrow0 = tid >> 3;          // 0..63
    const int lch   = (tid & 7) * 16;    // byte chunk in 128B row

    auto loadStage = [&](int st, int k0) {
        uint32_t sb = ub + st * 65536;
        #pragma unroll
        for (int j = 0; j < 2; j++) {
            int row = lrow0 + j * 64;
            uint32_t so = swz(row * 128 + lch);
            size_t ga = (size_t)(m0 + row) * K + k0 + (lch >> 1);
            size_t gb = (size_t)(n0 + row) * K + k0 + (lch >> 1);
            CP16(sb + so,         Ah + ga);
            CP16(sb + 16384 + so, Al + ga);
            CP16(sb + 32768 + so, Bh + gb);
            CP16(sb + 49152 + so, Bl + gb);
        }
        asm volatile("cp.async.commit_group;" ::: "memory");
    };

    // fragment lane addressing
    const int aRow = wm * 32 + (lane & 15);
    const int aKh  = (lane >> 4) * 16;                       // byte offset within 32B k16 span
    const int bRow = wn * 32 + (lane & 7) + ((lane & 16) >> 1);
    const int bKh  = ((lane >> 3) & 1) * 16;

    float c[2][4][4] = {};

    loadStage(0, 0);

    for (int cc = 0; cc < nch; cc++) {
        if (cc + 1 < nch) loadStage((cc + 1) & 1, (cc + 1) * 64);
        if (cc + 1 < nch) asm volatile("cp.async.wait_group 1;" ::: "memory");
        else              asm volatile("cp.async.wait_group 0;" ::: "memory");
        __syncthreads();

        uint32_t uA  = ub + (cc & 1) * 65536;
        uint32_t uAl = uA + 16384;
        uint32_t uBh = uA + 32768;
        uint32_t uBl = uA + 49152;

        #pragma unroll
        for (int s = 0; s < 4; s++) {
            uint32_t ah[2][4], al[2][4], bh[2][4], bl[2][4];
            #pragma unroll
            for (int mt = 0; mt < 2; mt++) {
                uint32_t ao = swz((aRow + mt * 16) * 128 + s * 32 + aKh);
                LDSM4(ah[mt], uA  + ao);
                LDSM4(al[mt], uAl + ao);
            }
            #pragma unroll
            for (int np = 0; np < 2; np++) {
                uint32_t bo = swz((bRow + np * 16) * 128 + s * 32 + bKh);
                LDSM4(bh[np], uBh + bo);
                LDSM4(bl[np], uBl + bo);
            }
            #pragma unroll
            for (int mt = 0; mt < 2; mt++)
                #pragma unroll
                for (int nt = 0; nt < 4; nt++) {
                    int np = nt >> 1, of = (nt & 1) * 2;
                    MMA_BF16(c[mt][nt], ah[mt], bh[np][of], bh[np][of + 1]);
                    MMA_BF16(c[mt][nt], ah[mt], bl[np][of], bl[np][of + 1]);
                    MMA_BF16(c[mt][nt], al[mt], bh[np][of], bh[np][of + 1]);
                }
        }
        __syncthreads();
    }

    const int gr = lane >> 2, gc = lane & 3;
    #pragma unroll
    for (int mt = 0; mt < 2; mt++) {
        #pragma unroll
        for (int nt = 0; nt < 4; nt++) {
            int row = m0 + wm * 32 + mt * 16 + gr;
            int col = n0 + wn * 32 + nt * 8 + gc * 2;
            float b0 = bias[col], b1 = bias[col + 1];
            if (row < M) {
                float2 v = make_float2(c[mt][nt][0] + b0, c[mt][nt][1] + b1);
                *(float2*)(C + (size_t)row * N + col) = v;
            }
            if (row + 8 < M) {
                float2 v = make_float2(c[mt][nt][2] + b0, c[mt][nt][3] + b1);
                *(float2*)(C + (size_t)(row + 8) * N + col) = v;
            }
        }
    }
}

// ---------------- CSR build ----------------
__global__ void hist_kernel(const int* __restrict__ edst) {
    int e = blockIdx.x * blockDim.x + threadIdx.x;
    if (e < E_NUM) atomicAdd(&g_deg[edst[e]], 1);
}

__global__ void scan_kernel() {
    __shared__ int sh[1024];
    __shared__ int carry;
    int tid = threadIdx.x;
    if (tid == 0) carry = 0;
    __syncthreads();
    for (int base = 0; base < N_DST; base += 1024) {
        int v = (base + tid < N_DST) ? g_deg[base + tid] : 0;
        sh[tid] = v;
        __syncthreads();
        #pragma unroll
        for (int off = 1; off < 1024; off <<= 1) {
            int t = (tid >= off) ? sh[tid - off] : 0;
            __syncthreads();
            sh[tid] += t;
            __syncthreads();
        }
        if (base + tid < N_DST) g_rowstart[base + tid] = carry + sh[tid] - v;
        __syncthreads();
        if (tid == 0) carry += sh[1023];
        __syncthreads();
    }
    if (threadIdx.x == 0) g_rowstart[N_DST] = E_NUM;
}

__global__ void fill_kernel(const int* __restrict__ esrc, const int* __restrict__ edst) {
    int e = blockIdx.x * blockDim.x + threadIdx.x;
    if (e >= E_NUM) return;
    int d = edst[e];
    int pos = atomicAdd(&g_cursor[d], 1);
    g_csrc[g_rowstart[d] + pos] = esrc[e];
}

// ---------------- fused GAT node kernel (online softmax) -> bf16 split output ----------------
__global__ __launch_bounds__(128)
void gat_node_kernel(const float* __restrict__ attn) {
    const int i    = blockIdx.x;
    const int warp = threadIdx.x >> 5;    // head
    const int lane = threadIdx.x & 31;
    const int fo   = warp * FPH + lane * 2;

    const int beg = g_rowstart[i];
    const int end = g_rowstart[i + 1];

    const float2 fd = *(const float2*)(g_fd + (size_t)i * HID + fo);
    const float2 at = *(const float2*)(attn + fo);

    float m = -INFINITY, den = 0.0f, ax = 0.0f, ay = 0.0f;

    if (beg < end) {
        int s = g_csrc[beg];
        float2 f = *(const float2*)(g_fs + (size_t)s * HID + fo);
        for (int j = beg; j < end; j++) {
            float2 fn;
            if (j + 1 < end) {
                int sn = g_csrc[j + 1];
                fn = *(const float2*)(g_fs + (size_t)sn * HID + fo);
            }
            float v0 = f.x + fd.x; v0 = fmaxf(v0, 0.2f * v0);
            float v1 = f.y + fd.y; v1 = fmaxf(v1, 0.2f * v1);
            float sc = fmaf(v0, at.x, v1 * at.y);
            #pragma unroll
            for (int o = 16; o; o >>= 1) sc += __shfl_xor_sync(0xffffffffu, sc, o);

            float mn  = fmaxf(m, sc);
            float scl = __expf(m - mn);
            float ex  = __expf(sc - mn);
            den = fmaf(den, scl, ex);
            ax  = fmaf(ax, scl, ex * f.x);
            ay  = fmaf(ay, scl, ex * f.y);
            m = mn;
            f = fn;
        }
    }

    float inv = (den > 0.0f) ? (1.0f / den) : 0.0f;
    float2 rs = *(const float2*)(g_res + (size_t)i * HID + fo);
    float ox = fmaxf(fmaf(ax, inv, rs.x), 0.0f);
    float oy = fmaxf(fmaf(ay, inv, rs.y), 0.0f);

    uint32_t xh, xl;
    bfsplit2(ox, oy, xh, xl);
    size_t off = ((size_t)i * HID + fo) >> 1;
    ((uint32_t*)s_x_h)[off] = xh;
    ((uint32_t*)s_x_l)[off] = xl;
}

// ---------------- fused GRU elementwise + logits head ----------------
#define LPAD 260

__global__ __launch_bounds__(256)
void gru_logits_kernel(const float* __restrict__ h0, const float* __restrict__ Wout,
                       const float* __restrict__ bout, float* __restrict__ hout,
                       float* __restrict__ out) {
    __shared__ float sh[16 * LPAD];
    __shared__ float sWt[16 * LPAD];
    int tid = threadIdx.x;
    for (int t = tid; t < HID * N_ACT; t += 256) {
        int k = t >> 4, c = t & 15;
        sWt[c * LPAD + k] = Wout[t];
    }
    int r   = tid >> 4;
    int row = blockIdx.x * 16 + r;
    int c0  = (tid & 15) * 16;

    if (row < N_DST) {
        size_t b  = (size_t)row * G3;
        size_t hb = (size_t)row * HID;
        #pragma unroll
        for (int q = 0; q < 16; q += 4) {
            int j = c0 + q;
            float4 gir = *(const float4*)(g_gi + b + j);
            float4 ghr = *(const float4*)(g_gh + b + j);
            float4 giz = *(const float4*)(g_gi + b + HID + j);
            float4 ghz = *(const float4*)(g_gh + b + HID + j);
            float4 gin = *(const float4*)(g_gi + b + 2 * HID + j);
            float4 ghn = *(const float4*)(g_gh + b + 2 * HID + j);
            float4 h   = *(const float4*)(h0 + hb + j);
            float4 o;
            {
                float rr = 1.0f / (1.0f + expf(-(gir.x + ghr.x)));
                float zz = 1.0f / (1.0f + expf(-(giz.x + ghz.x)));
                float nn = tanhf(gin.x + rr * ghn.x);
                o.x = (1.0f - zz) * nn + zz * h.x;
            }
            {
                float rr = 1.0f / (1.0f + expf(-(gir.y + ghr.y)));
                float zz = 1.0f / (1.0f + expf(-(giz.y + ghz.y)));
                float nn = tanhf(gin.y + rr * ghn.y);
                o.y = (1.0f - zz) * nn + zz * h.y;
            }
            {
                float rr = 1.0f / (1.0f + expf(-(gir.z + ghr.z)));
                float zz = 1.0f / (1.0f + expf(-(giz.z + ghz.z)));
                float nn = tanhf(gin.z + rr * ghn.z);
                o.z = (1.0f - zz) * nn + zz * h.z;
            }
            {
                float rr = 1.0f / (1.0f + expf(-(gir.w + ghr.w)));
                float zz = 1.0f / (1.0f + expf(-(giz.w + ghz.w)));
                float nn = tanhf(gin.w + rr * ghn.w);
                o.w = (1.0f - zz) * nn + zz * h.w;
            }
            *(float4*)(hout + hb + j) = o;
            *(float4*)&sh[r * LPAD + j] = o;
        }
    }
    __syncthreads();

    if (row < N_DST) {
        int col = tid & 15;
        float acc = bout[col];
        const float4* hv = (const float4*)&sh[r * LPAD];
        const float4* wv = (const float4*)&sWt[col * LPAD];
        #pragma unroll
        for (int k4 = 0; k4 < HID / 4; k4++) {
            float4 a = hv[k4], w = wv[k4];
            acc = fmaf(a.x, w.x, acc);
            acc = fmaf(a.y, w.y, acc);
            acc = fmaf(a.z, w.z, acc);
            acc = fmaf(a.w, w.w, acc);
        }
        out[(size_t)row * N_ACT + col] = acc;
    }
}

// ---------------- launch ----------------
extern "C" void kernel_launch(void* const* d_in, const int* in_sizes, int n_in,
                              void* d_out, int out_size) {
    const float* feat_gt    = (const float*)d_in[0];
    const float* feat_agent = (const float*)d_in[1];
    const float* h0         = (const float*)d_in[2];
    const int*   edge_src   = (const int*)d_in[3];
    const int*   edge_dst   = (const int*)d_in[4];
    const float* W_src      = (const float*)d_in[5];
    const float* b_src      = (const float*)d_in[6];
    const float* W_dst      = (const float*)d_in[7];
    const float* b_dst      = (const float*)d_in[8];
    const float* attn       = (const float*)d_in[9];
    const float* W_res      = (const float*)d_in[10];
    const float* b_res      = (const float*)d_in[11];
    const float* W_ih       = (const float*)d_in[12];
    const float* W_hh       = (const float*)d_in[13];
    const float* b_ih       = (const float*)d_in[14];
    const float* b_hh       = (const float*)d_in[15];
    const float* W_out      = (const float*)d_in[16];
    const float* b_out      = (const float*)d_in[17];

    float* out_logits = (float*)d_out;
    float* out_h      = (float*)d_out + (size_t)N_DST * N_ACT;

    float *p_fs, *p_fd, *p_res, *p_gi, *p_gh;
    int *p_deg, *p_cur;
    cudaGetSymbolAddress((void**)&p_fs,  g_fs);
    cudaGetSymbolAddress((void**)&p_fd,  g_fd);
    cudaGetSymbolAddress((void**)&p_res, g_res);
    cudaGetSymbolAddress((void**)&p_gi,  g_gi);
    cudaGetSymbolAddress((void**)&p_gh,  g_gh);
    cudaGetSymbolAddress((void**)&p_deg, g_deg);
    cudaGetSymbolAddress((void**)&p_cur, g_cursor);

    __nv_bfloat16 *pgt_h, *pgt_l, *pag_h, *pag_l, *px_h, *px_l, *ph_h, *ph_l;
    __nv_bfloat16 *pws_h, *pws_l, *pwd_h, *pwd_l, *pwr_h, *pwr_l, *pwi_h, *pwi_l, *pwh_h, *pwh_l;
    cudaGetSymbolAddress((void**)&pgt_h, s_gt_h); cudaGetSymbolAddress((void**)&pgt_l, s_gt_l);
    cudaGetSymbolAddress((void**)&pag_h, s_ag_h); cudaGetSymbolAddress((void**)&pag_l, s_ag_l);
    cudaGetSymbolAddress((void**)&px_h,  s_x_h);  cudaGetSymbolAddress((void**)&px_l,  s_x_l);
    cudaGetSymbolAddress((void**)&ph_h,  s_h_h);  cudaGetSymbolAddress((void**)&ph_l,  s_h_l);
    cudaGetSymbolAddress((void**)&pws_h, s_ws_h); cudaGetSymbolAddress((void**)&pws_l, s_ws_l);
    cudaGetSymbolAddress((void**)&pwd_h, s_wd_h); cudaGetSymbolAddress((void**)&pwd_l, s_wd_l);
    cudaGetSymbolAddress((void**)&pwr_h, s_wr_h); cudaGetSymbolAddress((void**)&pwr_l, s_wr_l);
    cudaGetSymbolAddress((void**)&pwi_h, s_wi_h); cudaGetSymbolAddress((void**)&pwi_l, s_wi_l);
    cudaGetSymbolAddress((void**)&pwh_h, s_wh_h); cudaGetSymbolAddress((void**)&pwh_l, s_wh_l);

    cudaFuncSetAttribute(tcbgemm, cudaFuncAttributeMaxDynamicSharedMemorySize, TCB_SMEM);

    const int MB = (N_DST + 127) / 128;   // 391

    // CSR build
    cudaMemsetAsync(p_deg, 0, N_DST * sizeof(int));
    cudaMemsetAsync(p_cur, 0, N_DST * sizeof(int));
    hist_kernel<<<(E_NUM + 255) / 256, 256>>>(edge_dst);
    scan_kernel<<<1, 1024>>>();
    fill_kernel<<<(E_NUM + 255) / 256, 256>>>(edge_src, edge_dst);

    // bf16 splits
    split_kernel<<<(N_SRC * D_IN / 4 + 255) / 256, 256>>>(feat_gt,    pgt_h, pgt_l, N_SRC * D_IN / 4);
    split_kernel<<<(N_DST * D_IN / 4 + 255) / 256, 256>>>(feat_agent, pag_h, pag_l, N_DST * D_IN / 4);
    split_kernel<<<(N_DST * HID / 4 + 255) / 256, 256>>>(h0,          ph_h,  ph_l,  N_DST * HID / 4);
    wsplit_t_kernel<<<64, 256>>>(W_src, pws_h, pws_l);
    wsplit_t_kernel<<<64, 256>>>(W_dst, pwd_h, pwd_l);
    wsplit_t_kernel<<<64, 256>>>(W_res, pwr_h, pwr_l);
    split_kernel<<<(G3 * HID / 4 + 255) / 256, 256>>>(W_ih, pwi_h, pwi_l, G3 * HID / 4);
    split_kernel<<<(G3 * HID / 4 + 255) / 256, 256>>>(W_hh, pwh_h, pwh_l, G3 * HID / 4);

    // feature projections (K=64, N=256)
    tcbgemm<<<dim3(HID / 128, MB), 512, TCB_SMEM>>>(pgt_h, pgt_l, pws_h, pws_l, b_src, p_fs,  N_SRC, HID, D_IN);
    tcbgemm<<<dim3(HID / 128, MB), 512, TCB_SMEM>>>(pag_h, pag_l, pwd_h, pwd_l, b_dst, p_fd,  N_DST, HID, D_IN);
    tcbgemm<<<dim3(HID / 128, MB), 512, TCB_SMEM>>>(pag_h, pag_l, pwr_h, pwr_l, b_res, p_res, N_DST, HID, D_IN);

    // fused GAT: online softmax + aggregation + residual + ReLU -> bf16 split x
    gat_node_kernel<<<N_DST, 128>>>(attn);

    // GRU gates (K=256, N=768)
    tcbgemm<<<dim3(G3 / 128, MB), 512, TCB_SMEM>>>(px_h, px_l, pwi_h, pwi_l, b_ih, p_gi, N_DST, G3, HID);
    tcbgemm<<<dim3(G3 / 128, MB), 512, TCB_SMEM>>>(ph_h, ph_l, pwh_h, pwh_l, b_hh, p_gh, N_DST, G3, HID);

    // fused GRU + logits
    gru_logits_kernel<<<(N_DST + 15) / 16, 256>>>(h0, W_out, b_out, out_h, out_logits);
}